// round 6
// baseline (speedup 1.0000x reference)
#include <cuda_runtime.h>
#include <cuda_bf16.h>
#include <cstdint>

#define BSZ 1024
#define HD  512
#define DH  256
#define BD  (BSZ*DH)

typedef unsigned long long u64;

// ---------------------------------------------------------------------------
// scratch (__device__ globals; no runtime allocation allowed)
// ---------------------------------------------------------------------------
__device__ float g_qproj[BSZ * HD];        // q_proj + ba
__device__ float g_part[8 * BD];           // per (g-tile, warp_n) logit partials
__device__ __nv_bfloat16 g_w_hi[HD * HD];  // Wah split high
__device__ __nv_bfloat16 g_w_lo[HD * HD];  // Wah split low

// ---------------------------------------------------------------------------
// helpers
// ---------------------------------------------------------------------------
__device__ __forceinline__ uint32_t smem_u32(const void* p) {
    uint32_t a;
    asm("{ .reg .u64 t; cvta.to.shared.u64 t, %1; cvt.u32.u64 %0, t; }"
        : "=r"(a) : "l"(p));
    return a;
}
__device__ __forceinline__ void cpa16(uint32_t dst, const void* src) {
    asm volatile("cp.async.cg.shared.global [%0], [%1], 16;" :: "r"(dst), "l"(src));
}
__device__ __forceinline__ void ldsm4(uint32_t* r, uint32_t addr) {
    asm volatile("ldmatrix.sync.aligned.m8n8.x4.shared.b16 {%0,%1,%2,%3}, [%4];"
        : "=r"(r[0]), "=r"(r[1]), "=r"(r[2]), "=r"(r[3]) : "r"(addr));
}
__device__ __forceinline__ void mma16816(float* c, const uint32_t* a, const uint32_t* b) {
    asm volatile(
        "mma.sync.aligned.m16n8k16.row.col.f32.bf16.bf16.f32 "
        "{%0,%1,%2,%3}, {%4,%5,%6,%7}, {%8,%9}, {%0,%1,%2,%3};"
        : "+f"(c[0]), "+f"(c[1]), "+f"(c[2]), "+f"(c[3])
        : "r"(a[0]), "r"(a[1]), "r"(a[2]), "r"(a[3]), "r"(b[0]), "r"(b[1]));
}
__device__ __forceinline__ float fast_tanh(float x) {
    float e = __expf(2.0f * x);
    return 1.0f - 2.0f / (e + 1.0f);
}

// ---------------------------------------------------------------------------
// convert_w: Wah fp32 -> bf16 hi/lo split (1 MB, trivial)
// ---------------------------------------------------------------------------
__global__ __launch_bounds__(256) void convert_w_kernel(const float* __restrict__ x) {
    int i = blockIdx.x * blockDim.x + threadIdx.x;
    float4 v = reinterpret_cast<const float4*>(x)[i];
    float vv[4] = {v.x, v.y, v.z, v.w};
    __nv_bfloat16 h[4], l[4];
#pragma unroll
    for (int j = 0; j < 4; j++) {
        h[j] = __float2bfloat16_rn(vv[j]);
        l[j] = __float2bfloat16_rn(vv[j] - __bfloat162float(h[j]));
    }
    __nv_bfloat162* hi2 = reinterpret_cast<__nv_bfloat162*>(g_w_hi);
    __nv_bfloat162* lo2 = reinterpret_cast<__nv_bfloat162*>(g_w_lo);
    hi2[2 * i]     = __halves2bfloat162(h[0], h[1]);
    hi2[2 * i + 1] = __halves2bfloat162(h[2], h[3]);
    lo2[2 * i]     = __halves2bfloat162(l[0], l[1]);
    lo2[2 * i + 1] = __halves2bfloat162(l[2], l[3]);
}

// ---------------------------------------------------------------------------
// qproj: M=1024 N=512 K=1024 fp32; 32x64 tiles -> 256 CTAs
// ---------------------------------------------------------------------------
#define QBK 32
__global__ __launch_bounds__(128) void qproj_kernel(
    const float* __restrict__ h_tilde, const float* __restrict__ c_t,
    const float* __restrict__ Waq, const float* __restrict__ ba)
{
    __shared__ float As[QBK][36];
    __shared__ float Bs[QBK][68];
    const int t  = threadIdx.x;
    const int tx = t & 15, ty = t >> 4;
    const int b0 = blockIdx.x * 32;
    const int g0 = blockIdx.y * 64;

    float acc[4][4] = {};

    for (int k0 = 0; k0 < 2 * HD; k0 += QBK) {
#pragma unroll
        for (int i = 0; i < 8; i++) {
            int idx = t + i * 128;
            int r = idx >> 5, c = idx & 31;
            int j = k0 + c;
            As[c][r] = (j < HD) ? h_tilde[(b0 + r) * HD + j]
                                : c_t[(b0 + r) * HD + (j - HD)];
        }
#pragma unroll
        for (int i = 0; i < 16; i++) {
            int idx = t + i * 128;
            int r = idx >> 5, c = idx & 31;
            Bs[c][r] = Waq[(g0 + r) * (2 * HD) + k0 + c];
        }
        __syncthreads();
#pragma unroll
        for (int k = 0; k < QBK; k++) {
            float4 av = *reinterpret_cast<const float4*>(&As[k][ty * 4]);
            float4 bv = *reinterpret_cast<const float4*>(&Bs[k][tx * 4]);
            float a[4] = {av.x, av.y, av.z, av.w};
            float bb[4] = {bv.x, bv.y, bv.z, bv.w};
#pragma unroll
            for (int i = 0; i < 4; i++)
#pragma unroll
                for (int jj = 0; jj < 4; jj++)
                    acc[i][jj] = fmaf(a[i], bb[jj], acc[i][jj]);
        }
        __syncthreads();
    }

#pragma unroll
    for (int i = 0; i < 4; i++)
#pragma unroll
        for (int jj = 0; jj < 4; jj++)
            g_qproj[(b0 + ty * 4 + i) * HD + (g0 + tx * 4 + jj)] =
                acc[i][jj] + ba[g0 + tx * 4 + jj];
}

// ---------------------------------------------------------------------------
// separator no-op (keeps score as the 4th launch for ncu capture)
// ---------------------------------------------------------------------------
__global__ void sep_kernel() {}

// ---------------------------------------------------------------------------
// score: HMMA GEMM, in-kernel fp32->bf16 hi/lo split of h_history.
// 3-stage SMEM buffering, ONE __syncthreads per K-chunk:
//   stage(c) = c % 3.
//   Safety: writes for chunk i+2 (cpB + later stsA for i+1) target stages
//   whose last readers were chunks i-1 / i-2, and all threads passed the
//   top-of-iteration barrier AFTER finishing those computes.
//   cp.async groups retire in commit order, so wait_group(1) at iter i
//   guarantees chunk-i B data has landed.
// ---------------------------------------------------------------------------
#define SSTR    40            // smem row stride in halves (80 B)
#define TILE_H  (128 * SSTR)  // halves per 128x32 tile
#define STAGE_H (4 * TILE_H)  // Ah, Al, Bh, Bl
#define NCHUNK  16            // 512/32
#define NSTAGE  3

__global__ __launch_bounds__(256) void score_mma_kernel(
    const float* __restrict__ hh, const float* __restrict__ v_t)
{
    extern __shared__ __nv_bfloat16 sm[];
    __shared__ float v_sh[128], qp_sh[128];

    const int t = threadIdx.x;
    const int l = t & 31, wid = t >> 5;
    const int warp_m = wid & 3;       // M offset 32*warp_m
    const int warp_n = wid >> 2;      // N offset 64*warp_n
    const int c2 = (l & 3) * 2;

    const int g0 = blockIdx.x * 128;  // fast dim -> A-tile L2 reuse (4 CTAs)
    const int m0 = blockIdx.y * 128;
    const int b  = m0 / DH;

    if (t < 128) {
        v_sh[t]  = v_t[g0 + t];
        qp_sh[t] = g_qproj[b * HD + g0 + t];
    }

    const float*         srcA  = hh + (size_t)m0 * HD;
    const __nv_bfloat16* srcBh = g_w_hi + (size_t)g0 * HD;
    const __nv_bfloat16* srcBl = g_w_lo + (size_t)g0 * HD;

    const uint32_t smem_base = smem_u32(sm);
    char* smc = reinterpret_cast<char*>(sm);

    float acc[2][8][4];
#pragma unroll
    for (int mt = 0; mt < 2; mt++)
#pragma unroll
        for (int nt = 0; nt < 8; nt++)
#pragma unroll
            for (int e = 0; e < 4; e++) acc[mt][nt][e] = 0.0f;

    // A chunk: 128 rows x 32 fp32 -> 1024 float4 tasks / 256 thr = 4
    auto ldgA = [&](int ch, float4* r) {
        const int k0 = ch * 32;
#pragma unroll
        for (int j = 0; j < 4; j++) {
            int task = t + j * 256;
            int row = task >> 3, sg = task & 7;
            r[j] = *reinterpret_cast<const float4*>(
                srcA + (size_t)row * HD + k0 + sg * 4);
        }
    };
    auto stsA = [&](int st, const float4* r) {
        const uint32_t base = (uint32_t)st * STAGE_H * 2;
#pragma unroll
        for (int j = 0; j < 4; j++) {
            int task = t + j * 256;
            int row = task >> 3, sg = task & 7;
            float4 v = r[j];
            __nv_bfloat162 h01 = __floats2bfloat162_rn(v.x, v.y);
            __nv_bfloat162 h23 = __floats2bfloat162_rn(v.z, v.w);
            __nv_bfloat162 l01 = __floats2bfloat162_rn(
                v.x - __bfloat162float(h01.x), v.y - __bfloat162float(h01.y));
            __nv_bfloat162 l23 = __floats2bfloat162_rn(
                v.z - __bfloat162float(h23.x), v.w - __bfloat162float(h23.y));
            uint2 hv = make_uint2(*(uint32_t*)&h01, *(uint32_t*)&h23);
            uint2 lv = make_uint2(*(uint32_t*)&l01, *(uint32_t*)&l23);
            uint32_t off = base + (uint32_t)(row * SSTR) * 2 + (uint32_t)sg * 8;
            *reinterpret_cast<uint2*>(smc + off)              = hv;
            *reinterpret_cast<uint2*>(smc + TILE_H * 2 + off) = lv;
        }
    };
    auto cpB = [&](int ch, int st) {
        const uint32_t base = smem_base + (uint32_t)st * STAGE_H * 2;
        const int k0 = ch * 32;
#pragma unroll
        for (int j = 0; j < 2; j++) {
            int task = t + j * 256;
            int row = task >> 2, seg = task & 3;
            uint32_t off = (uint32_t)(row * SSTR) * 2 + (uint32_t)seg * 16;
            size_t so = (size_t)row * HD + k0 + seg * 8;
            cpa16(base + 2 * TILE_H * 2 + off, srcBh + so);
            cpa16(base + 3 * TILE_H * 2 + off, srcBl + so);
        }
        asm volatile("cp.async.commit_group;" ::: "memory");
    };

    auto compute = [&](int st) {
        const uint32_t sb = smem_base + (uint32_t)st * STAGE_H * 2;
#pragma unroll
        for (int ks = 0; ks < 2; ks++) {
            const int kb = ks * 16;
            uint32_t a_hi[2][4], a_lo[2][4], b_hi[4][4], b_lo[4][4];
#pragma unroll
            for (int mt = 0; mt < 2; mt++) {
                int row = warp_m * 32 + mt * 16 + (l & 7) + ((l >> 3) & 1) * 8;
                int col = kb + ((l >> 4) & 1) * 8;
                uint32_t off = (uint32_t)(row * SSTR + col) * 2;
                ldsm4(a_hi[mt], sb + off);
                ldsm4(a_lo[mt], sb + TILE_H * 2 + off);
            }
#pragma unroll
            for (int p = 0; p < 4; p++) {
                int n = warp_n * 64 + p * 16 + (l & 7) + ((l >> 4) & 1) * 8;
                int col = kb + ((l >> 3) & 1) * 8;
                uint32_t off = (uint32_t)(n * SSTR + col) * 2;
                ldsm4(b_hi[p], sb + 2 * TILE_H * 2 + off);
                ldsm4(b_lo[p], sb + 3 * TILE_H * 2 + off);
            }
#pragma unroll
            for (int p = 0; p < 4; p++)
#pragma unroll
                for (int h = 0; h < 2; h++)
#pragma unroll
                    for (int mt = 0; mt < 2; mt++)
                        mma16816(acc[mt][2 * p + h], a_hi[mt], &b_hi[p][2 * h]);
#pragma unroll
            for (int p = 0; p < 4; p++)
#pragma unroll
                for (int h = 0; h < 2; h++)
#pragma unroll
                    for (int mt = 0; mt < 2; mt++)
                        mma16816(acc[mt][2 * p + h], a_hi[mt], &b_lo[p][2 * h]);
#pragma unroll
            for (int p = 0; p < 4; p++)
#pragma unroll
                for (int h = 0; h < 2; h++)
#pragma unroll
                    for (int mt = 0; mt < 2; mt++)
                        mma16816(acc[mt][2 * p + h], a_lo[mt], &b_hi[p][2 * h]);
        }
    };

    // prologue: chunk c lives in rA[c&1] until STS'd; stage(c) = c%3
    float4 regA[2][4];
    ldgA(0, regA[0]);
    ldgA(1, regA[1]);
    stsA(0, regA[0]);
    cpB(0, 0);
    cpB(1, 1);

#pragma unroll 1
    for (int i = 0; i < NCHUNK; i++) {
        const int s = i % NSTAGE;
        if (i + 1 < NCHUNK) {
            asm volatile("cp.async.wait_group 1;" ::: "memory");
        } else {
            asm volatile("cp.async.wait_group 0;" ::: "memory");
        }
        __syncthreads();   // stage s fully ready; prior readers of target stages done
        if (i + 2 < NCHUNK) {
            ldgA(i + 2, regA[i & 1]);          // chunk i's A already in smem
            cpB(i + 2, (i + 2) % NSTAGE);      // last reader was compute(i-1)
        }
        compute(s);
        if (i + 1 < NCHUNK)
            stsA((i + 1) % NSTAGE, regA[(i + 1) & 1]); // last reader compute(i-2)
    }

    // epilogue: tanh + v-dot, quad reduce, plain store into partial slice
    const int slice = blockIdx.x * 2 + warp_n;     // 0..7
    const int q = l >> 2;
#pragma unroll
    for (int mt = 0; mt < 2; mt++) {
        float rs0 = 0.0f, rs1 = 0.0f;
#pragma unroll
        for (int nt = 0; nt < 8; nt++) {
            const int gbase = warp_n * 64 + nt * 8 + c2;
            const float vq0 = v_sh[gbase],     qq0 = qp_sh[gbase];
            const float vq1 = v_sh[gbase + 1], qq1 = qp_sh[gbase + 1];
            rs0 += vq0 * fast_tanh(acc[mt][nt][0] + qq0);
            rs0 += vq1 * fast_tanh(acc[mt][nt][1] + qq1);
            rs1 += vq0 * fast_tanh(acc[mt][nt][2] + qq0);
            rs1 += vq1 * fast_tanh(acc[mt][nt][3] + qq1);
        }
        rs0 += __shfl_xor_sync(0xffffffffu, rs0, 1);
        rs0 += __shfl_xor_sync(0xffffffffu, rs0, 2);
        rs1 += __shfl_xor_sync(0xffffffffu, rs1, 1);
        rs1 += __shfl_xor_sync(0xffffffffu, rs1, 2);
        if ((l & 3) == 0) {
            const int rowb = m0 + warp_m * 32 + mt * 16 + q;
            g_part[slice * BD + rowb]     = rs0;
            g_part[slice * BD + rowb + 8] = rs1;
        }
    }
}

// ---------------------------------------------------------------------------
// softmax: sum 8 partial slices, then softmax over d
// ---------------------------------------------------------------------------
__global__ __launch_bounds__(DH) void softmax_kernel(float* __restrict__ alpha_out)
{
    __shared__ float red[DH];
    const int b = blockIdx.x, d = threadIdx.x;
    const int row = b * DH + d;
    float x = 0.0f;
#pragma unroll
    for (int s = 0; s < 8; s++) x += g_part[s * BD + row];
    red[d] = x;
    __syncthreads();
    for (int s = DH / 2; s > 0; s >>= 1) {
        if (d < s) red[d] = fmaxf(red[d], red[d + s]);
        __syncthreads();
    }
    float mx = red[0];
    __syncthreads();
    float e = __expf(x - mx);
    red[d] = e;
    __syncthreads();
    for (int s = DH / 2; s > 0; s >>= 1) {
        if (d < s) red[d] += red[d + s];
        __syncthreads();
    }
    alpha_out[row] = e / red[0];
}

// ---------------------------------------------------------------------------
// e_t = alpha . h_history  — 128 thr x float4, full-row coalesced
// ---------------------------------------------------------------------------
__global__ __launch_bounds__(128) void et_kernel(
    const float* __restrict__ hh, const float* __restrict__ alpha,
    float* __restrict__ e_out)
{
    __shared__ float al[DH];
    const int b = blockIdx.x, t = threadIdx.x;
    al[t]       = alpha[b * DH + t];
    al[t + 128] = alpha[b * DH + t + 128];
    __syncthreads();
    const float4* basep = reinterpret_cast<const float4*>(
        hh + (size_t)b * DH * HD) + t;
    float ax = 0.f, ay = 0.f, az = 0.f, aw = 0.f;
#pragma unroll 4
    for (int d = 0; d < DH; d++) {
        float4 v = basep[(size_t)d * (HD / 4)];
        float a = al[d];
        ax = fmaf(a, v.x, ax);
        ay = fmaf(a, v.y, ay);
        az = fmaf(a, v.z, az);
        aw = fmaf(a, v.w, aw);
    }
    reinterpret_cast<float4*>(e_out + b * HD)[t] = make_float4(ax, ay, az, aw);
}

// ---------------------------------------------------------------------------
// launch
// inputs: 0 h_tilde | 1 c_t | 2 h_history | 3 Waq | 4 Wah | 5 ba | 6 v_t
// out = [e_t (B*H) | alpha (B*D)]
// ---------------------------------------------------------------------------
extern "C" void kernel_launch(void* const* d_in, const int* in_sizes, int n_in,
                              void* d_out, int out_size)
{
    const float* h_tilde = (const float*)d_in[0];
    const float* c_t     = (const float*)d_in[1];
    const float* hh      = (const float*)d_in[2];
    const float* Waq     = (const float*)d_in[3];
    const float* Wah     = (const float*)d_in[4];
    const float* ba      = (const float*)d_in[5];
    const float* v_t     = (const float*)d_in[6];

    float* out       = (float*)d_out;
    float* e_out     = out;               // [B, H]
    float* alpha_out = out + BSZ * HD;    // [B, D]

    cudaFuncSetAttribute(score_mma_kernel,
                         cudaFuncAttributeMaxDynamicSharedMemorySize,
                         NSTAGE * STAGE_H * 2);

    convert_w_kernel<<<(HD * HD / 4) / 256, 256>>>(Wah);          // 1

    dim3 g1(BSZ / 32, HD / 64);
    qproj_kernel<<<g1, 128>>>(h_tilde, c_t, Waq, ba);             // 2

    sep_kernel<<<1, 32>>>();                                      // 3

    dim3 g2(HD / 128, BD / 128);   // g0 fastest -> A-tile L2 reuse
    score_mma_kernel<<<g2, 256, NSTAGE * STAGE_H * 2>>>(hh, v_t); // 4 (profiled)

    softmax_kernel<<<BSZ, DH>>>(alpha_out);                       // 5

    et_kernel<<<BSZ, 128>>>(hh, alpha_out, e_out);                // 6
}

// round 7
// speedup vs baseline: 1.4288x; 1.4288x over previous
#include <cuda_runtime.h>
#include <cuda_bf16.h>
#include <cstdint>

#define BSZ 1024
#define HD  512
#define DH  256
#define BD  (BSZ*DH)

typedef unsigned long long u64;

// ---------------------------------------------------------------------------
// scratch (__device__ globals; no runtime allocation allowed)
// ---------------------------------------------------------------------------
__device__ float g_qproj[BSZ * HD];        // q_proj + ba
__device__ float g_part[16 * BD];          // per (g-tile, warp_n) logit partials
__device__ __nv_bfloat16 g_w_hi[HD * HD];  // Wah split high
__device__ __nv_bfloat16 g_w_lo[HD * HD];  // Wah split low

// ---------------------------------------------------------------------------
// helpers
// ---------------------------------------------------------------------------
__device__ __forceinline__ uint32_t smem_u32(const void* p) {
    uint32_t a;
    asm("{ .reg .u64 t; cvta.to.shared.u64 t, %1; cvt.u32.u64 %0, t; }"
        : "=r"(a) : "l"(p));
    return a;
}
__device__ __forceinline__ void cpa16(uint32_t dst, const void* src) {
    asm volatile("cp.async.cg.shared.global [%0], [%1], 16;" :: "r"(dst), "l"(src));
}
__device__ __forceinline__ void ldsm4(uint32_t* r, uint32_t addr) {
    asm volatile("ldmatrix.sync.aligned.m8n8.x4.shared.b16 {%0,%1,%2,%3}, [%4];"
        : "=r"(r[0]), "=r"(r[1]), "=r"(r[2]), "=r"(r[3]) : "r"(addr));
}
__device__ __forceinline__ void mma16816(float* c, const uint32_t* a, const uint32_t* b) {
    asm volatile(
        "mma.sync.aligned.m16n8k16.row.col.f32.bf16.bf16.f32 "
        "{%0,%1,%2,%3}, {%4,%5,%6,%7}, {%8,%9}, {%0,%1,%2,%3};"
        : "+f"(c[0]), "+f"(c[1]), "+f"(c[2]), "+f"(c[3])
        : "r"(a[0]), "r"(a[1]), "r"(a[2]), "r"(a[3]), "r"(b[0]), "r"(b[1]));
}
__device__ __forceinline__ float fast_tanh(float x) {
    float e = __expf(2.0f * x);
    return 1.0f - 2.0f / (e + 1.0f);
}

// ---------------------------------------------------------------------------
// convert_w: Wah fp32 -> bf16 hi/lo split (1 MB, trivial)
// ---------------------------------------------------------------------------
__global__ __launch_bounds__(256) void convert_w_kernel(const float* __restrict__ x) {
    int i = blockIdx.x * blockDim.x + threadIdx.x;
    float4 v = reinterpret_cast<const float4*>(x)[i];
    float vv[4] = {v.x, v.y, v.z, v.w};
    __nv_bfloat16 h[4], l[4];
#pragma unroll
    for (int j = 0; j < 4; j++) {
        h[j] = __float2bfloat16_rn(vv[j]);
        l[j] = __float2bfloat16_rn(vv[j] - __bfloat162float(h[j]));
    }
    __nv_bfloat162* hi2 = reinterpret_cast<__nv_bfloat162*>(g_w_hi);
    __nv_bfloat162* lo2 = reinterpret_cast<__nv_bfloat162*>(g_w_lo);
    hi2[2 * i]     = __halves2bfloat162(h[0], h[1]);
    hi2[2 * i + 1] = __halves2bfloat162(h[2], h[3]);
    lo2[2 * i]     = __halves2bfloat162(l[0], l[1]);
    lo2[2 * i + 1] = __halves2bfloat162(l[2], l[3]);
}

// ---------------------------------------------------------------------------
// qproj: M=1024 N=512 K=1024 fp32; 32x64 tiles -> 256 CTAs
// ---------------------------------------------------------------------------
#define QBK 32
__global__ __launch_bounds__(128) void qproj_kernel(
    const float* __restrict__ h_tilde, const float* __restrict__ c_t,
    const float* __restrict__ Waq, const float* __restrict__ ba)
{
    __shared__ float As[QBK][36];
    __shared__ float Bs[QBK][68];
    const int t  = threadIdx.x;
    const int tx = t & 15, ty = t >> 4;
    const int b0 = blockIdx.x * 32;
    const int g0 = blockIdx.y * 64;

    float acc[4][4] = {};

    for (int k0 = 0; k0 < 2 * HD; k0 += QBK) {
#pragma unroll
        for (int i = 0; i < 8; i++) {
            int idx = t + i * 128;
            int r = idx >> 5, c = idx & 31;
            int j = k0 + c;
            As[c][r] = (j < HD) ? h_tilde[(b0 + r) * HD + j]
                                : c_t[(b0 + r) * HD + (j - HD)];
        }
#pragma unroll
        for (int i = 0; i < 16; i++) {
            int idx = t + i * 128;
            int r = idx >> 5, c = idx & 31;
            Bs[c][r] = Waq[(g0 + r) * (2 * HD) + k0 + c];
        }
        __syncthreads();
#pragma unroll
        for (int k = 0; k < QBK; k++) {
            float4 av = *reinterpret_cast<const float4*>(&As[k][ty * 4]);
            float4 bv = *reinterpret_cast<const float4*>(&Bs[k][tx * 4]);
            float a[4] = {av.x, av.y, av.z, av.w};
            float bb[4] = {bv.x, bv.y, bv.z, bv.w};
#pragma unroll
            for (int i = 0; i < 4; i++)
#pragma unroll
                for (int jj = 0; jj < 4; jj++)
                    acc[i][jj] = fmaf(a[i], bb[jj], acc[i][jj]);
        }
        __syncthreads();
    }

#pragma unroll
    for (int i = 0; i < 4; i++)
#pragma unroll
        for (int jj = 0; jj < 4; jj++)
            g_qproj[(b0 + ty * 4 + i) * HD + (g0 + tx * 4 + jj)] =
                acc[i][jj] + ba[g0 + tx * 4 + jj];
}

// ---------------------------------------------------------------------------
// separator no-op (keeps score as the 4th launch for ncu capture)
// ---------------------------------------------------------------------------
__global__ void sep_kernel() {}

// ---------------------------------------------------------------------------
// score: HMMA GEMM, in-kernel fp32->bf16 hi/lo split of h_history.
// CTA tile 128(M) x 64(N), 8 warps (4M x 2N), warp tile 32x32.
// R4-proven 2-stage scheduling (two barriers/chunk). Small tile -> regs<=128
// (__launch_bounds__(256,2)) -> 2 CTAs/SM: cross-CTA overlap hides bubbles.
// ---------------------------------------------------------------------------
#define SSTR    40                 // smem row stride in halves (80 B)
#define TILE_A  (128 * SSTR)       // halves per A tile (128 x 32)
#define TILE_B  (64 * SSTR)        // halves per B tile (64 x 32)
#define STAGE_H (2*TILE_A + 2*TILE_B)  // Ah, Al, Bh, Bl = 15360 halves
#define OFF_AL  TILE_A
#define OFF_BH  (2*TILE_A)
#define OFF_BL  (2*TILE_A + TILE_B)
#define NCHUNK  16                 // 512/32

__global__ __launch_bounds__(256, 2) void score_mma_kernel(
    const float* __restrict__ hh, const float* __restrict__ v_t)
{
    extern __shared__ __nv_bfloat16 sm[];
    __shared__ float v_sh[64], qp_sh[64];

    const int t = threadIdx.x;
    const int l = t & 31, wid = t >> 5;
    const int warp_m = wid & 3;       // M offset 32*warp_m
    const int warp_n = wid >> 2;      // N offset 32*warp_n
    const int c2 = (l & 3) * 2;

    const int g0 = blockIdx.x * 64;   // fast dim -> A-tile L2 reuse (8 CTAs)
    const int m0 = blockIdx.y * 128;
    const int b  = m0 / DH;

    if (t < 64) {
        v_sh[t]  = v_t[g0 + t];
        qp_sh[t] = g_qproj[b * HD + g0 + t];
    }

    const float*         srcA  = hh + (size_t)m0 * HD;
    const __nv_bfloat16* srcBh = g_w_hi + (size_t)g0 * HD;
    const __nv_bfloat16* srcBl = g_w_lo + (size_t)g0 * HD;

    const uint32_t smem_base = smem_u32(sm);
    char* smc = reinterpret_cast<char*>(sm);

    float acc[2][4][4];               // [mt][nt][elem], warp tile 32x32
#pragma unroll
    for (int mt = 0; mt < 2; mt++)
#pragma unroll
        for (int nt = 0; nt < 4; nt++)
#pragma unroll
            for (int e = 0; e < 4; e++) acc[mt][nt][e] = 0.0f;

    // A chunk: 128 rows x 32 fp32 -> 1024 float4 tasks / 256 thr = 4
    auto ldgA = [&](int ch, float4* r) {
        const int k0 = ch * 32;
#pragma unroll
        for (int j = 0; j < 4; j++) {
            int task = t + j * 256;
            int row = task >> 3, sg = task & 7;
            r[j] = *reinterpret_cast<const float4*>(
                srcA + (size_t)row * HD + k0 + sg * 4);
        }
    };
    auto stsA = [&](int st, const float4* r) {
        const uint32_t base = (uint32_t)st * STAGE_H * 2;
#pragma unroll
        for (int j = 0; j < 4; j++) {
            int task = t + j * 256;
            int row = task >> 3, sg = task & 7;
            float4 v = r[j];
            __nv_bfloat162 h01 = __floats2bfloat162_rn(v.x, v.y);
            __nv_bfloat162 h23 = __floats2bfloat162_rn(v.z, v.w);
            __nv_bfloat162 l01 = __floats2bfloat162_rn(
                v.x - __bfloat162float(h01.x), v.y - __bfloat162float(h01.y));
            __nv_bfloat162 l23 = __floats2bfloat162_rn(
                v.z - __bfloat162float(h23.x), v.w - __bfloat162float(h23.y));
            uint2 hv = make_uint2(*(uint32_t*)&h01, *(uint32_t*)&h23);
            uint2 lv = make_uint2(*(uint32_t*)&l01, *(uint32_t*)&l23);
            uint32_t off = base + (uint32_t)(row * SSTR) * 2 + (uint32_t)sg * 8;
            *reinterpret_cast<uint2*>(smc + off)              = hv;
            *reinterpret_cast<uint2*>(smc + OFF_AL * 2 + off) = lv;
        }
    };
    // B chunk: 2 tiles of 64 rows x 32 halves -> 256 tasks, 1/thread/tile
    auto cpB = [&](int ch, int st) {
        const uint32_t base = smem_base + (uint32_t)st * STAGE_H * 2;
        const int k0 = ch * 32;
        int row = t >> 2, seg = t & 3;
        uint32_t off = (uint32_t)(row * SSTR) * 2 + (uint32_t)seg * 16;
        size_t so = (size_t)row * HD + k0 + seg * 8;
        cpa16(base + OFF_BH * 2 + off, srcBh + so);
        cpa16(base + OFF_BL * 2 + off, srcBl + so);
        asm volatile("cp.async.commit_group;" ::: "memory");
    };

    auto compute = [&](int st) {
        const uint32_t sb = smem_base + (uint32_t)st * STAGE_H * 2;
#pragma unroll
        for (int ks = 0; ks < 2; ks++) {
            const int kb = ks * 16;
            uint32_t a_hi[2][4], a_lo[2][4], b_hi[2][4], b_lo[2][4];
#pragma unroll
            for (int mt = 0; mt < 2; mt++) {
                int row = warp_m * 32 + mt * 16 + (l & 7) + ((l >> 3) & 1) * 8;
                int col = kb + ((l >> 4) & 1) * 8;
                uint32_t off = (uint32_t)(row * SSTR + col) * 2;
                ldsm4(a_hi[mt], sb + off);
                ldsm4(a_lo[mt], sb + OFF_AL * 2 + off);
            }
#pragma unroll
            for (int p = 0; p < 2; p++) {
                int n = warp_n * 32 + p * 16 + (l & 7) + ((l >> 4) & 1) * 8;
                int col = kb + ((l >> 3) & 1) * 8;
                uint32_t off = (uint32_t)(n * SSTR + col) * 2;
                ldsm4(b_hi[p], sb + OFF_BH * 2 + off);
                ldsm4(b_lo[p], sb + OFF_BL * 2 + off);
            }
            // 3 split products, acc reuse distance = 8 MMAs
#pragma unroll
            for (int p = 0; p < 2; p++)
#pragma unroll
                for (int h = 0; h < 2; h++)
#pragma unroll
                    for (int mt = 0; mt < 2; mt++)
                        mma16816(acc[mt][2 * p + h], a_hi[mt], &b_hi[p][2 * h]);
#pragma unroll
            for (int p = 0; p < 2; p++)
#pragma unroll
                for (int h = 0; h < 2; h++)
#pragma unroll
                    for (int mt = 0; mt < 2; mt++)
                        mma16816(acc[mt][2 * p + h], a_hi[mt], &b_lo[p][2 * h]);
#pragma unroll
            for (int p = 0; p < 2; p++)
#pragma unroll
                for (int h = 0; h < 2; h++)
#pragma unroll
                    for (int mt = 0; mt < 2; mt++)
                        mma16816(acc[mt][2 * p + h], a_lo[mt], &b_hi[p][2 * h]);
        }
    };

    float4 regA[4];
    ldgA(0, regA);
    cpB(0, 0);

#pragma unroll 1
    for (int i = 0; i < NCHUNK; i++) {
        const int s = i & 1;
        stsA(s, regA);
        if (i + 1 < NCHUNK) {
            ldgA(i + 1, regA);
            cpB(i + 1, s ^ 1);
            asm volatile("cp.async.wait_group 1;" ::: "memory");
        } else {
            asm volatile("cp.async.wait_group 0;" ::: "memory");
        }
        __syncthreads();
        compute(s);
        __syncthreads();
    }

    // epilogue: tanh + v-dot, quad reduce, plain store into partial slice
    const int slice = blockIdx.x * 2 + warp_n;     // 0..15
    const int q = l >> 2;
#pragma unroll
    for (int mt = 0; mt < 2; mt++) {
        float rs0 = 0.0f, rs1 = 0.0f;
#pragma unroll
        for (int nt = 0; nt < 4; nt++) {
            const int gbase = warp_n * 32 + nt * 8 + c2;
            const float vq0 = v_sh[gbase],     qq0 = qp_sh[gbase];
            const float vq1 = v_sh[gbase + 1], qq1 = qp_sh[gbase + 1];
            rs0 += vq0 * fast_tanh(acc[mt][nt][0] + qq0);
            rs0 += vq1 * fast_tanh(acc[mt][nt][1] + qq1);
            rs1 += vq0 * fast_tanh(acc[mt][nt][2] + qq0);
            rs1 += vq1 * fast_tanh(acc[mt][nt][3] + qq1);
        }
        rs0 += __shfl_xor_sync(0xffffffffu, rs0, 1);
        rs0 += __shfl_xor_sync(0xffffffffu, rs0, 2);
        rs1 += __shfl_xor_sync(0xffffffffu, rs1, 1);
        rs1 += __shfl_xor_sync(0xffffffffu, rs1, 2);
        if ((l & 3) == 0) {
            const int rowb = m0 + warp_m * 32 + mt * 16 + q;
            g_part[(size_t)slice * BD + rowb]     = rs0;
            g_part[(size_t)slice * BD + rowb + 8] = rs1;
        }
    }
}

// ---------------------------------------------------------------------------
// softmax: sum 16 partial slices, then softmax over d
// ---------------------------------------------------------------------------
__global__ __launch_bounds__(DH) void softmax_kernel(float* __restrict__ alpha_out)
{
    __shared__ float red[DH];
    const int b = blockIdx.x, d = threadIdx.x;
    const int row = b * DH + d;
    float x = 0.0f;
#pragma unroll
    for (int s = 0; s < 16; s++) x += g_part[(size_t)s * BD + row];
    red[d] = x;
    __syncthreads();
    for (int s = DH / 2; s > 0; s >>= 1) {
        if (d < s) red[d] = fmaxf(red[d], red[d + s]);
        __syncthreads();
    }
    float mx = red[0];
    __syncthreads();
    float e = __expf(x - mx);
    red[d] = e;
    __syncthreads();
    for (int s = DH / 2; s > 0; s >>= 1) {
        if (d < s) red[d] += red[d + s];
        __syncthreads();
    }
    alpha_out[row] = e / red[0];
}

// ---------------------------------------------------------------------------
// e_t = alpha . h_history  — 128 thr x float4, full-row coalesced
// ---------------------------------------------------------------------------
__global__ __launch_bounds__(128) void et_kernel(
    const float* __restrict__ hh, const float* __restrict__ alpha,
    float* __restrict__ e_out)
{
    __shared__ float al[DH];
    const int b = blockIdx.x, t = threadIdx.x;
    al[t]       = alpha[b * DH + t];
    al[t + 128] = alpha[b * DH + t + 128];
    __syncthreads();
    const float4* basep = reinterpret_cast<const float4*>(
        hh + (size_t)b * DH * HD) + t;
    float ax = 0.f, ay = 0.f, az = 0.f, aw = 0.f;
#pragma unroll 4
    for (int d = 0; d < DH; d++) {
        float4 v = basep[(size_t)d * (HD / 4)];
        float a = al[d];
        ax = fmaf(a, v.x, ax);
        ay = fmaf(a, v.y, ay);
        az = fmaf(a, v.z, az);
        aw = fmaf(a, v.w, aw);
    }
    reinterpret_cast<float4*>(e_out + b * HD)[t] = make_float4(ax, ay, az, aw);
}

// ---------------------------------------------------------------------------
// launch
// inputs: 0 h_tilde | 1 c_t | 2 h_history | 3 Waq | 4 Wah | 5 ba | 6 v_t
// out = [e_t (B*H) | alpha (B*D)]
// ---------------------------------------------------------------------------
extern "C" void kernel_launch(void* const* d_in, const int* in_sizes, int n_in,
                              void* d_out, int out_size)
{
    const float* h_tilde = (const float*)d_in[0];
    const float* c_t     = (const float*)d_in[1];
    const float* hh      = (const float*)d_in[2];
    const float* Waq     = (const float*)d_in[3];
    const float* Wah     = (const float*)d_in[4];
    const float* ba      = (const float*)d_in[5];
    const float* v_t     = (const float*)d_in[6];

    float* out       = (float*)d_out;
    float* e_out     = out;               // [B, H]
    float* alpha_out = out + BSZ * HD;    // [B, D]

    cudaFuncSetAttribute(score_mma_kernel,
                         cudaFuncAttributeMaxDynamicSharedMemorySize,
                         2 * STAGE_H * 2);

    convert_w_kernel<<<(HD * HD / 4) / 256, 256>>>(Wah);          // 1

    dim3 g1(BSZ / 32, HD / 64);
    qproj_kernel<<<g1, 128>>>(h_tilde, c_t, Waq, ba);             // 2

    sep_kernel<<<1, 32>>>();                                      // 3

    dim3 g2(HD / 64, BD / 128);    // g0 fastest -> A-tile L2 reuse (8 CTAs)
    score_mma_kernel<<<g2, 256, 2 * STAGE_H * 2>>>(hh, v_t);      // 4 (profiled)

    softmax_kernel<<<BSZ, DH>>>(alpha_out);                       // 5

    et_kernel<<<BSZ, 128>>>(hh, alpha_out, e_out);                // 6
}